// round 7
// baseline (speedup 1.0000x reference)
#include <cuda_runtime.h>
#include <math.h>
#include <stdint.h>

#define BATCH 8192
#define NRSS  12
#define NLED  256
#define NBLK  444   // 148 SMs * 3 CTAs
#define NT    128   // threads per CTA; each thread owns 2 LEDs; 2 batches/iter

// ---- folded weights (computed once per launch by fold_kernel) ----
__device__ float g_WcT[32 * 64];  // WcT[j][i] = sum_d qf_w2[i,d]*kp_w2[j,d]
__device__ float g_v[64];         // v[i] = sum_d qf_w2[i,d]*kp_b2[d]
__device__ float g_bc[32];        // bc[j] = sum_d qf_b2[d]*kp_w2[j,d]
__device__ float g_c0[1];         // c0 = qf_b2 . kp_b2

__global__ void fold_kernel(const float* __restrict__ qf_w2, const float* __restrict__ qf_b2,
                            const float* __restrict__ kp_w2, const float* __restrict__ kp_b2) {
    int e = blockIdx.x * blockDim.x + threadIdx.x;
    if (e < 2048) {
        int j = e >> 6, i = e & 63;
        float acc = 0.f;
        #pragma unroll 8
        for (int d = 0; d < 128; d++) acc += qf_w2[i * 128 + d] * kp_w2[j * 128 + d];
        g_WcT[j * 64 + i] = acc;
    }
    if (e < 64) {
        float acc = 0.f;
        #pragma unroll 8
        for (int d = 0; d < 128; d++) acc += qf_w2[e * 128 + d] * kp_b2[d];
        g_v[e] = acc;
    } else if (e < 96) {
        int j = e - 64;
        float acc = 0.f;
        #pragma unroll 8
        for (int d = 0; d < 128; d++) acc += qf_b2[d] * kp_w2[j * 128 + d];
        g_bc[j] = acc;
    } else if (e == 96) {
        float acc = 0.f;
        for (int d = 0; d < 128; d++) acc += qf_b2[d] * kp_b2[d];
        g_c0[0] = acc;
    }
}

// ---- shared memory layout (dynamic); ~74KB -> 3 CTAs/SM ----
struct SMem {
    float me1T[64 * 132];     // me1T[j*132+i] = me_w1[i,j]
    float me2T[32 * 68];      // me2T[j*68+i]  = me_w2[i,j]
    float qf1mc[64 * 36];     // qf1mc[j*36+i] = qf_w1[1+i,j]
    float WcT [32 * 68];
    float h1q [2][12 * 68];   // dual-buffered per-batch scratch
    float kp1 [11 * 32];
    float Qh  [2][12 * 32];
    float kpb1[32];
    float Ls  [2][128];
    float mc  [2][32];
    float h1m [2][64];
    float red [96];           // [0..47] warp maxes, [48..95] warp sums
    float rss [2][NRSS];
    float cw  [2][NRSS];
    float qc  [2][NRSS];
    float prev[2][3];
    float inv2s2[2];
};

__device__ __forceinline__ float wredmax(float v) {
    #pragma unroll
    for (int o = 16; o; o >>= 1) v = fmaxf(v, __shfl_xor_sync(0xffffffffu, v, o));
    return v;
}
__device__ __forceinline__ float wredsum(float v) {
    #pragma unroll
    for (int o = 16; o; o >>= 1) v += __shfl_xor_sync(0xffffffffu, v, o);
    return v;
}
__device__ __forceinline__ float dot4(float4 a, float4 b) {
    return a.x * b.x + a.y * b.y + a.z * b.z + a.w * b.w;
}

__global__ __launch_bounds__(NT, 3)
void cah_kernel(const float* __restrict__ rss_t,
                const float* __restrict__ led_f,
                const float* __restrict__ led_p,
                const float* __restrict__ prevp,
                const int*   __restrict__ fmask,
                const float* __restrict__ lstm,
                const float* __restrict__ me_w1, const float* __restrict__ me_b1,
                const float* __restrict__ me_w2, const float* __restrict__ me_b2,
                const float* __restrict__ ci_w,  const float* __restrict__ ci_b,
                const float* __restrict__ qf_w1, const float* __restrict__ qf_b1,
                const float* __restrict__ kp_w1, const float* __restrict__ kp_b1,
                const float* __restrict__ ss_w,  const float* __restrict__ ss_b,
                float* __restrict__ out) {
    extern __shared__ float smraw[];
    SMem& sm = *reinterpret_cast<SMem*>(smraw);
    const int tid = threadIdx.x, lane = tid & 31, wid = tid >> 5;
    const float NEG_INF = __int_as_float(0xff800000);

    // ---- stage weights once per CTA ----
    for (int idx = tid; idx < 128 * 64; idx += NT) { int i = idx >> 6, j = idx & 63; sm.me1T[j * 132 + i] = me_w1[idx]; }
    for (int idx = tid; idx < 64 * 32;  idx += NT) { int i = idx >> 5, j = idx & 31; sm.me2T[j * 68 + i] = me_w2[idx]; }
    for (int idx = tid; idx < 32 * 64;  idx += NT) { int i = idx >> 6, j = idx & 63; sm.qf1mc[j * 36 + i] = qf_w1[(i + 1) * 64 + j]; }
    for (int idx = tid; idx < 32 * 64;  idx += NT) { int j = idx >> 6, i = idx & 63; sm.WcT[j * 68 + i] = g_WcT[idx]; }
    for (int idx = tid; idx < 11 * 32;  idx += NT) sm.kp1[idx] = kp_w1[idx];
    if (tid < 32) sm.kpb1[tid] = kp_b1[tid];

    // per-thread mask bits for LEDs ka=tid, kb=tid+128 (same for all batches)
    uint32_t mba = 0, mbb = 0;
    #pragma unroll
    for (int q = 0; q < NRSS; q++) {
        mba |= (fmask[q * NLED + tid] != 0 ? 1u : 0u) << q;
        mbb |= (fmask[q * NLED + tid + 128] != 0 ? 1u : 0u) << q;
    }
    __syncthreads();

    for (int p = blockIdx.x; p < BATCH / 2; p += gridDim.x) {
        const int b0 = 2 * p, b1 = 2 * p + 1;

        // prefetch LED data for both batches, both LEDs (consumed in score phase)
        float4 f0[2], f1[2], g0[2], g1[2];
        float pax[2], pay[2], paz[2], pbx[2], pby[2], pbz[2];
        #pragma unroll
        for (int bb = 0; bb < 2; bb++) {
            int b = b0 + bb;
            const float4* lfa = reinterpret_cast<const float4*>(led_f + ((size_t)b * NLED + tid) * 8);
            const float4* lfb = reinterpret_cast<const float4*>(led_f + ((size_t)b * NLED + tid + 128) * 8);
            f0[bb] = lfa[0]; f1[bb] = lfa[1];
            g0[bb] = lfb[0]; g1[bb] = lfb[1];
            const float* ppa = led_p + ((size_t)b * NLED + tid) * 3;
            const float* ppb = led_p + ((size_t)b * NLED + tid + 128) * 3;
            pax[bb] = ppa[0]; pay[bb] = ppa[1]; paz[bb] = ppa[2];
            pbx[bb] = ppb[0]; pby[bb] = ppb[1]; pbz[bb] = ppb[2];
        }

        // load per-batch small inputs
        if (tid < 32) {
            reinterpret_cast<float4*>(sm.Ls[0])[tid] =
                reinterpret_cast<const float4*>(lstm + (size_t)b0 * 128)[tid];
        } else if (tid < 64) {
            reinterpret_cast<float4*>(sm.Ls[1])[tid - 32] =
                reinterpret_cast<const float4*>(lstm + (size_t)b1 * 128)[tid - 32];
        } else if (tid < 76)  sm.rss[0][tid - 64] = rss_t[(size_t)b0 * NRSS + (tid - 64)];
        else if (tid < 88)    sm.rss[1][tid - 76] = rss_t[(size_t)b1 * NRSS + (tid - 76)];
        else if (tid < 91)    sm.prev[0][tid - 88] = prevp[(size_t)b0 * 3 + (tid - 88)];
        else if (tid < 94)    sm.prev[1][tid - 91] = prevp[(size_t)b1 * 3 + (tid - 91)];
        __syncthreads();

        // h1m for both batches: 128 threads fully used
        {
            int bb = tid >> 6, j = tid & 63;
            float a0 = __ldg(&me_b1[j]), a1 = 0.f;
            const float4* r = reinterpret_cast<const float4*>(&sm.me1T[j * 132]);
            const float4* L = reinterpret_cast<const float4*>(sm.Ls[bb]);
            #pragma unroll
            for (int i = 0; i < 32; i += 2) { a0 += dot4(L[i], r[i]); a1 += dot4(L[i + 1], r[i + 1]); }
            sm.h1m[bb][j] = fmaxf(a0 + a1, 0.f);
        }
        __syncthreads();

        // mc for both batches: 64 threads
        if (tid < 64) {
            int bb = tid >> 5, j = tid & 31;
            float a0 = __ldg(&me_b2[j]), a1 = 0.f;
            const float4* r = reinterpret_cast<const float4*>(&sm.me2T[j * 68]);
            const float4* hm = reinterpret_cast<const float4*>(sm.h1m[bb]);
            #pragma unroll
            for (int i = 0; i < 16; i += 2) { a0 += dot4(hm[i], r[i]); a1 += dot4(hm[i + 1], r[i + 1]); }
            sm.mc[bb][j] = a0 + a1;
        }
        __syncthreads();

        // channel weights + sigma (tid<26) overlapped with h1q (all 128 threads)
        if (tid < 24) {
            int bb = tid / 12, q = tid - bb * 12;
            float acc = __ldg(&ci_b[q]);
            #pragma unroll
            for (int i = 0; i < 32; i++) acc += sm.mc[bb][i] * __ldg(&ci_w[i * 12 + q]);
            float c = 1.f / (1.f + __expf(-acc));
            sm.cw[bb][q] = c;
            out[(size_t)BATCH * NRSS * NLED + (size_t)(b0 + bb) * NRSS + q] = c;
        } else if (tid < 26) {
            int bb = tid - 24;
            float x = __ldg(&ss_b[0]);
            #pragma unroll
            for (int i = 0; i < 32; i++) x += sm.mc[bb][i] * __ldg(&ss_w[i]);
            float sp = fmaxf(x, 0.f) + log1pf(__expf(-fabsf(x)));
            float sg = sp + 0.5f;
            sm.inv2s2[bb] = 0.5f / (sg * sg);
        }

        // h1q: fixed j = tid&63, q in {2p' + (tid>>6)}; weight row cached once,
        // reused for both batches (12 outputs per thread)
        {
            int j = tid & 63, hi = tid >> 6;
            float4 wr[8];
            const float4* r = reinterpret_cast<const float4*>(&sm.qf1mc[j * 36]);
            #pragma unroll
            for (int i = 0; i < 8; i++) wr[i] = r[i];
            float w0 = __ldg(&qf_w1[j]), bj = __ldg(&qf_b1[j]);
            #pragma unroll
            for (int bb = 0; bb < 2; bb++) {
                float4 mcr[8];
                const float4* m4 = reinterpret_cast<const float4*>(sm.mc[bb]);
                #pragma unroll
                for (int i = 0; i < 8; i++) mcr[i] = m4[i];
                #pragma unroll
                for (int pp = 0; pp < 6; pp++) {
                    int q = 2 * pp + hi;
                    float a0 = bj + sm.rss[bb][q] * w0, a1 = 0.f;
                    #pragma unroll
                    for (int i = 0; i < 8; i += 2) { a0 += dot4(mcr[i], wr[i]); a1 += dot4(mcr[i + 1], wr[i + 1]); }
                    sm.h1q[bb][q * 68 + j] = fmaxf(a0 + a1, 0.f);
                }
            }
        }
        __syncthreads();

        // Qh[bb][q][32] = cw*(h1q @ Wc + bc); WcT row cached, reused for 6 outputs
        {
            int j = tid & 31, qo = tid >> 5;
            float4 wr[16];
            const float4* r = reinterpret_cast<const float4*>(&sm.WcT[j * 68]);
            #pragma unroll
            for (int i = 0; i < 16; i++) wr[i] = r[i];
            float bj = g_bc[j];
            #pragma unroll
            for (int bb = 0; bb < 2; bb++) {
                #pragma unroll
                for (int pp = 0; pp < 3; pp++) {
                    int q = 4 * pp + qo;
                    const float4* hq = reinterpret_cast<const float4*>(&sm.h1q[bb][q * 68]);
                    float a0 = bj, a1 = 0.f;
                    #pragma unroll
                    for (int i = 0; i < 16; i += 2) { a0 += dot4(hq[i], wr[i]); a1 += dot4(hq[i + 1], wr[i + 1]); }
                    sm.Qh[bb][(q << 5) + j] = (a0 + a1) * sm.cw[bb][q];
                }
            }
            if (tid < 24) {  // qc
                int bb = tid / 12, q = tid - bb * 12;
                const float4* hq = reinterpret_cast<const float4*>(&sm.h1q[bb][q * 68]);
                const float4* v4 = reinterpret_cast<const float4*>(g_v);
                float a0 = g_c0[0], a1 = 0.f;
                #pragma unroll
                for (int i = 0; i < 16; i += 2) { a0 += dot4(hq[i], v4[i]); a1 += dot4(hq[i + 1], v4[i + 1]); }
                sm.qc[bb][q] = (a0 + a1) * sm.cw[bb][q];
            }
        }
        __syncthreads();

        // score + softmax per batch (2 barriers each)
        #pragma unroll
        for (int bb = 0; bb < 2; bb++) {
            float kina[11] = {f0[bb].x, f0[bb].y, f0[bb].z, f0[bb].w,
                              f1[bb].x, f1[bb].y, f1[bb].z, f1[bb].w,
                              pax[bb], pay[bb], paz[bb]};
            float kinb[11] = {g0[bb].x, g0[bb].y, g0[bb].z, g0[bb].w,
                              g1[bb].x, g1[bb].y, g1[bb].z, g1[bb].w,
                              pbx[bb], pby[bb], pbz[bb]};
            float ha[32], hb[32];
            {
                const float4* bp = (const float4*)sm.kpb1;
                #pragma unroll
                for (int jj = 0; jj < 8; jj++) {
                    float4 w = bp[jj];
                    ha[4 * jj] = w.x; ha[4 * jj + 1] = w.y; ha[4 * jj + 2] = w.z; ha[4 * jj + 3] = w.w;
                    hb[4 * jj] = w.x; hb[4 * jj + 1] = w.y; hb[4 * jj + 2] = w.z; hb[4 * jj + 3] = w.w;
                }
            }
            #pragma unroll
            for (int i = 0; i < 11; i++) {
                float ta = kina[i], tb = kinb[i];
                const float4* wp = (const float4*)&sm.kp1[i * 32];
                #pragma unroll
                for (int jj = 0; jj < 8; jj++) {
                    float4 w = wp[jj];
                    ha[4 * jj]     += ta * w.x; hb[4 * jj]     += tb * w.x;
                    ha[4 * jj + 1] += ta * w.y; hb[4 * jj + 1] += tb * w.y;
                    ha[4 * jj + 2] += ta * w.z; hb[4 * jj + 2] += tb * w.z;
                    ha[4 * jj + 3] += ta * w.w; hb[4 * jj + 3] += tb * w.w;
                }
            }
            #pragma unroll
            for (int j = 0; j < 32; j++) { ha[j] = fmaxf(ha[j], 0.f); hb[j] = fmaxf(hb[j], 0.f); }

            float dax = sm.prev[bb][0] - pax[bb], day = sm.prev[bb][1] - pay[bb], daz = sm.prev[bb][2] - paz[bb];
            float dbx = sm.prev[bb][0] - pbx[bb], dby = sm.prev[bb][1] - pby[bb], dbz = sm.prev[bb][2] - pbz[bb];
            float dba = (dax * dax + day * day + daz * daz) * sm.inv2s2[bb];
            float dbb = (dbx * dbx + dby * dby + dbz * dbz) * sm.inv2s2[bb];

            float sa[NRSS], sb[NRSS];
            #pragma unroll
            for (int q = 0; q < NRSS; q++) {
                float aa = sm.qc[bb][q], ab = aa;
                const float4* wp = (const float4*)&sm.Qh[bb][q * 32];
                #pragma unroll
                for (int jj = 0; jj < 8; jj++) {
                    float4 w = wp[jj];
                    aa += w.x * ha[4 * jj] + w.y * ha[4 * jj + 1] + w.z * ha[4 * jj + 2] + w.w * ha[4 * jj + 3];
                    ab += w.x * hb[4 * jj] + w.y * hb[4 * jj + 1] + w.z * hb[4 * jj + 2] + w.w * hb[4 * jj + 3];
                }
                sa[q] = ((mba >> q) & 1) ? (aa - dba) : NEG_INF;
                sb[q] = ((mbb >> q) & 1) ? (ab - dbb) : NEG_INF;
            }

            // softmax: 2 barriers. red[0..47]=warp maxes, red[48..95]=warp sums
            #pragma unroll
            for (int q = 0; q < NRSS; q++) {
                float m = wredmax(fmaxf(sa[q], sb[q]));
                if (lane == 0) sm.red[q * 4 + wid] = m;
            }
            __syncthreads();
            #pragma unroll
            for (int q = 0; q < NRSS; q++) {
                float m = fmaxf(fmaxf(sm.red[q * 4], sm.red[q * 4 + 1]),
                                fmaxf(sm.red[q * 4 + 2], sm.red[q * 4 + 3]));
                float ea = __expf(sa[q] - m), eb = __expf(sb[q] - m);
                sa[q] = ea; sb[q] = eb;
                float s = wredsum(ea + eb);
                if (lane == 0) sm.red[48 + q * 4 + wid] = s;
            }
            __syncthreads();
            #pragma unroll
            for (int q = 0; q < NRSS; q++) {
                float s = (sm.red[48 + q * 4] + sm.red[48 + q * 4 + 1]) +
                          (sm.red[48 + q * 4 + 2] + sm.red[48 + q * 4 + 3]);
                float inv = __frcp_rn(s);
                size_t base = ((size_t)(b0 + bb) * NRSS + q) << 8;
                out[base + tid] = sa[q] * inv;
                out[base + tid + 128] = sb[q] * inv;
            }
        }
        // no trailing barrier needed: next-iter load phase only writes
        // Ls/rss/prev, none of which are read after the Qh barrier.
    }
}

extern "C" void kernel_launch(void* const* d_in, const int* in_sizes, int n_in,
                              void* d_out, int out_size) {
    (void)in_sizes; (void)n_in; (void)out_size;
    const float* rss_t  = (const float*)d_in[0];
    const float* led_f  = (const float*)d_in[1];
    const float* led_p  = (const float*)d_in[2];
    const float* prevp  = (const float*)d_in[3];
    const int*   fmask  = (const int*)  d_in[4];
    const float* lstm   = (const float*)d_in[5];
    const float* me_w1  = (const float*)d_in[6];
    const float* me_b1  = (const float*)d_in[7];
    const float* me_w2  = (const float*)d_in[8];
    const float* me_b2  = (const float*)d_in[9];
    const float* ci_w   = (const float*)d_in[10];
    const float* ci_b   = (const float*)d_in[11];
    const float* qf_w1  = (const float*)d_in[12];
    const float* qf_b1  = (const float*)d_in[13];
    const float* qf_w2  = (const float*)d_in[14];
    const float* qf_b2  = (const float*)d_in[15];
    const float* kp_w1  = (const float*)d_in[16];
    const float* kp_b1  = (const float*)d_in[17];
    const float* kp_w2  = (const float*)d_in[18];
    const float* kp_b2  = (const float*)d_in[19];
    const float* ss_w   = (const float*)d_in[20];
    const float* ss_b   = (const float*)d_in[21];
    float* out = (float*)d_out;

    static int smem_set = 0;
    if (!smem_set) {
        cudaFuncSetAttribute(cah_kernel, cudaFuncAttributeMaxDynamicSharedMemorySize,
                             (int)sizeof(SMem));
        smem_set = 1;
    }

    fold_kernel<<<8, 256>>>(qf_w2, qf_b2, kp_w2, kp_b2);
    cah_kernel<<<NBLK, NT, sizeof(SMem)>>>(rss_t, led_f, led_p, prevp, fmask, lstm,
                                           me_w1, me_b1, me_w2, me_b2, ci_w, ci_b,
                                           qf_w1, qf_b1, kp_w1, kp_b1, ss_w, ss_b, out);
}

// round 9
// speedup vs baseline: 1.0735x; 1.0735x over previous
#include <cuda_runtime.h>
#include <math.h>
#include <stdint.h>

#define BATCH 8192
#define NRSS  12
#define NLED  256
#define NBLK  592   // 148 SMs * 4 CTAs
#define NT    128   // threads per CTA; each thread owns 2 LEDs

// ---- folded weights (computed once per launch by fold_kernel) ----
__device__ float g_WcT[32 * 64];  // WcT[j][i] = sum_d qf_w2[i,d]*kp_w2[j,d]
__device__ float g_v[64];         // v[i] = sum_d qf_w2[i,d]*kp_b2[d]
__device__ float g_bc[32];        // bc[j] = sum_d qf_b2[d]*kp_w2[j,d]
__device__ float g_c0[1];         // c0 = qf_b2 . kp_b2

__global__ void fold_kernel(const float* __restrict__ qf_w2, const float* __restrict__ qf_b2,
                            const float* __restrict__ kp_w2, const float* __restrict__ kp_b2) {
    int e = blockIdx.x * blockDim.x + threadIdx.x;
    if (e < 2048) {
        int j = e >> 6, i = e & 63;
        float acc = 0.f;
        #pragma unroll 8
        for (int d = 0; d < 128; d++) acc += qf_w2[i * 128 + d] * kp_w2[j * 128 + d];
        g_WcT[j * 64 + i] = acc;
    }
    if (e < 64) {
        float acc = 0.f;
        #pragma unroll 8
        for (int d = 0; d < 128; d++) acc += qf_w2[e * 128 + d] * kp_b2[d];
        g_v[e] = acc;
    } else if (e < 96) {
        int j = e - 64;
        float acc = 0.f;
        #pragma unroll 8
        for (int d = 0; d < 128; d++) acc += qf_b2[d] * kp_w2[j * 128 + d];
        g_bc[j] = acc;
    } else if (e == 96) {
        float acc = 0.f;
        for (int d = 0; d < 128; d++) acc += qf_b2[d] * kp_b2[d];
        g_c0[0] = acc;
    }
}

// ---- shared memory layout (dynamic); ~50KB -> 4 CTAs/SM ----
struct SMem {
    float me1T[64 * 132];   // me1T[j*132+i] = me_w1[i,j]  (33.8KB)
    float WcT [32 * 68];    // WcT[j*68+i]                 (8.7KB)
    float h1q [12 * 68];    // per-iter scratch
    float kp1 [11 * 32];
    float Qh  [12 * 32];
    float kpb1[32];
    float Ls  [128];
    float mc  [32];
    float h1m [64];
    float red [96];         // [0..47] warp maxes, [48..95] warp sums
    float rss [NRSS];
    float cw  [NRSS];
    float qc  [NRSS];
    float prev[3];
    float inv2s2;
};

__device__ __forceinline__ float wredmax(float v) {
    #pragma unroll
    for (int o = 16; o; o >>= 1) v = fmaxf(v, __shfl_xor_sync(0xffffffffu, v, o));
    return v;
}
__device__ __forceinline__ float wredsum(float v) {
    #pragma unroll
    for (int o = 16; o; o >>= 1) v += __shfl_xor_sync(0xffffffffu, v, o);
    return v;
}
__device__ __forceinline__ float dot4(float4 a, float4 b) {
    return a.x * b.x + a.y * b.y + a.z * b.z + a.w * b.w;
}

__global__ __launch_bounds__(NT, 4)
void cah_kernel(const float* __restrict__ rss_t,
                const float* __restrict__ led_f,
                const float* __restrict__ led_p,
                const float* __restrict__ prevp,
                const int*   __restrict__ fmask,
                const float* __restrict__ lstm,
                const float* __restrict__ me_w1, const float* __restrict__ me_b1,
                const float* __restrict__ me_w2, const float* __restrict__ me_b2,
                const float* __restrict__ ci_w,  const float* __restrict__ ci_b,
                const float* __restrict__ qf_w1, const float* __restrict__ qf_b1,
                const float* __restrict__ kp_w1, const float* __restrict__ kp_b1,
                const float* __restrict__ ss_w,  const float* __restrict__ ss_b,
                float* __restrict__ out) {
    extern __shared__ float smraw[];
    SMem& sm = *reinterpret_cast<SMem*>(smraw);
    const int tid = threadIdx.x, lane = tid & 31, wid = tid >> 5;
    const float NEG_INF = __int_as_float(0xff800000);

    // ---- stage weights once per CTA ----
    for (int idx = tid; idx < 128 * 64; idx += NT) { int i = idx >> 6, j = idx & 63; sm.me1T[j * 132 + i] = me_w1[idx]; }
    for (int idx = tid; idx < 32 * 64;  idx += NT) { int j = idx >> 6, i = idx & 63; sm.WcT[j * 68 + i] = g_WcT[idx]; }
    for (int idx = tid; idx < 11 * 32;  idx += NT) sm.kp1[idx] = kp_w1[idx];
    if (tid < 32) sm.kpb1[tid] = kp_b1[tid];

    // per-thread mask bits for LEDs ka=tid, kb=tid+128
    uint32_t mba = 0, mbb = 0;
    #pragma unroll
    for (int q = 0; q < NRSS; q++) {
        mba |= (fmask[q * NLED + tid] != 0 ? 1u : 0u) << q;
        mbb |= (fmask[q * NLED + tid + 128] != 0 ? 1u : 0u) << q;
    }
    __syncthreads();

    const float4* Ls4  = reinterpret_cast<const float4*>(sm.Ls);

    for (int b = blockIdx.x; b < BATCH; b += gridDim.x) {
        // prefetch this thread's 2 LEDs (overlaps all the small phases)
        const float4* lfa = reinterpret_cast<const float4*>(led_f + ((size_t)b * NLED + tid) * 8);
        const float4* lfb = reinterpret_cast<const float4*>(led_f + ((size_t)b * NLED + tid + 128) * 8);
        float4 fa0 = lfa[0], fa1 = lfa[1];
        float4 fb0 = lfb[0], fb1 = lfb[1];
        const float* ppa = led_p + ((size_t)b * NLED + tid) * 3;
        const float* ppb = led_p + ((size_t)b * NLED + tid + 128) * 3;
        float pax = ppa[0], pay = ppa[1], paz = ppa[2];
        float pbx = ppb[0], pby = ppb[1], pbz = ppb[2];

        if (tid < 32) {
            reinterpret_cast<float4*>(sm.Ls)[tid] =
                reinterpret_cast<const float4*>(lstm + (size_t)b * 128)[tid];
        } else if (tid < 44) sm.rss[tid - 32] = rss_t[(size_t)b * NRSS + (tid - 32)];
        else if (tid < 47)  sm.prev[tid - 44] = prevp[(size_t)b * 3 + (tid - 44)];
        __syncthreads();

        // h1m = relu(Ls @ me_w1 + b1)  [64] from smem me1T (conflict-free f4)
        if (tid < 64) {
            float a0 = __ldg(&me_b1[tid]), a1 = 0.f;
            const float4* r = reinterpret_cast<const float4*>(&sm.me1T[tid * 132]);
            #pragma unroll
            for (int i = 0; i < 32; i += 2) { a0 += dot4(Ls4[i], r[i]); a1 += dot4(Ls4[i + 1], r[i + 1]); }
            sm.h1m[tid] = fmaxf(a0 + a1, 0.f);
        }
        __syncthreads();

        // mc = h1m @ me_w2 + b2 [32]; me_w2 streamed from global (coalesced, L2-hot)
        if (tid < 32) {
            float a0 = __ldg(&me_b2[tid]), a1 = 0.f;
            #pragma unroll 8
            for (int i = 0; i < 64; i += 2) {
                a0 += sm.h1m[i]     * __ldg(&me_w2[i * 32 + tid]);
                a1 += sm.h1m[i + 1] * __ldg(&me_w2[(i + 1) * 32 + tid]);
            }
            sm.mc[tid] = a0 + a1;
        }
        __syncthreads();

        // channel weights + sigma (tid<13) overlapped with h1q (all threads)
        if (tid < 12) {
            float acc = __ldg(&ci_b[tid]);
            #pragma unroll
            for (int i = 0; i < 32; i++) acc += sm.mc[i] * __ldg(&ci_w[i * 12 + tid]);
            float c = 1.f / (1.f + __expf(-acc));
            sm.cw[tid] = c;
            out[(size_t)BATCH * NRSS * NLED + (size_t)b * NRSS + tid] = c;
        } else if (tid == 12) {
            float x = __ldg(&ss_b[0]);
            #pragma unroll
            for (int i = 0; i < 32; i++) x += sm.mc[i] * __ldg(&ss_w[i]);
            float sp = fmaxf(x, 0.f) + log1pf(__expf(-fabsf(x)));
            float sg = sp + 0.5f;
            sm.inv2s2 = 0.5f / (sg * sg);
        }

        // h1q: fixed j = tid&63, q in {2p + (tid>>6)}; weight column cached from
        // global (coalesced across warp, L2-hot), mc streamed from smem broadcast
        {
            int j = tid & 63, hi = tid >> 6;
            float wr[32];
            #pragma unroll
            for (int i = 0; i < 32; i++) wr[i] = __ldg(&qf_w1[(i + 1) * 64 + j]);
            float w0 = __ldg(&qf_w1[j]), bj = __ldg(&qf_b1[j]);
            const float4* m4 = reinterpret_cast<const float4*>(sm.mc);
            #pragma unroll
            for (int p = 0; p < 6; p++) {
                int q = 2 * p + hi;
                float a0 = bj + sm.rss[q] * w0, a1 = 0.f;
                #pragma unroll
                for (int i = 0; i < 8; i += 2) {
                    float4 m0 = m4[i], m1 = m4[i + 1];
                    a0 += m0.x * wr[4 * i] + m0.y * wr[4 * i + 1] + m0.z * wr[4 * i + 2] + m0.w * wr[4 * i + 3];
                    a1 += m1.x * wr[4 * i + 4] + m1.y * wr[4 * i + 5] + m1.z * wr[4 * i + 6] + m1.w * wr[4 * i + 7];
                }
                sm.h1q[q * 68 + j] = fmaxf(a0 + a1, 0.f);
            }
        }
        __syncthreads();

        // Qh[q][32] = cw[q]*(h1q @ Wc + bc); WcT row streamed from smem (no reg cache)
        {
            int j = tid & 31, qo = tid >> 5;
            float bj = g_bc[j];
            const float4* r = reinterpret_cast<const float4*>(&sm.WcT[j * 68]);
            #pragma unroll
            for (int p = 0; p < 3; p++) {
                int q = 4 * p + qo;
                const float4* hq = reinterpret_cast<const float4*>(&sm.h1q[q * 68]);
                float a0 = bj, a1 = 0.f;
                #pragma unroll
                for (int i = 0; i < 16; i += 2) { a0 += dot4(hq[i], r[i]); a1 += dot4(hq[i + 1], r[i + 1]); }
                sm.Qh[(q << 5) + j] = (a0 + a1) * sm.cw[q];
            }
            if (tid < 12) {  // qc[q]
                const float4* hq = reinterpret_cast<const float4*>(&sm.h1q[tid * 68]);
                const float4* v4 = reinterpret_cast<const float4*>(g_v);
                float a0 = g_c0[0], a1 = 0.f;
                #pragma unroll
                for (int i = 0; i < 16; i += 2) { a0 += dot4(hq[i], v4[i]); a1 += dot4(hq[i + 1], v4[i + 1]); }
                sm.qc[tid] = (a0 + a1) * sm.cw[tid];
            }
        }
        __syncthreads();

        // H rows for both LEDs; every broadcast load feeds 2 FMAs
        float kina[11] = {fa0.x, fa0.y, fa0.z, fa0.w, fa1.x, fa1.y, fa1.z, fa1.w, pax, pay, paz};
        float kinb[11] = {fb0.x, fb0.y, fb0.z, fb0.w, fb1.x, fb1.y, fb1.z, fb1.w, pbx, pby, pbz};
        float ha[32], hb[32];
        {
            const float4* bp = (const float4*)sm.kpb1;
            #pragma unroll
            for (int jj = 0; jj < 8; jj++) {
                float4 w = bp[jj];
                ha[4 * jj] = w.x; ha[4 * jj + 1] = w.y; ha[4 * jj + 2] = w.z; ha[4 * jj + 3] = w.w;
                hb[4 * jj] = w.x; hb[4 * jj + 1] = w.y; hb[4 * jj + 2] = w.z; hb[4 * jj + 3] = w.w;
            }
        }
        #pragma unroll
        for (int i = 0; i < 11; i++) {
            float ta = kina[i], tb = kinb[i];
            const float4* wp = (const float4*)&sm.kp1[i * 32];
            #pragma unroll
            for (int jj = 0; jj < 8; jj++) {
                float4 w = wp[jj];
                ha[4 * jj]     += ta * w.x; hb[4 * jj]     += tb * w.x;
                ha[4 * jj + 1] += ta * w.y; hb[4 * jj + 1] += tb * w.y;
                ha[4 * jj + 2] += ta * w.z; hb[4 * jj + 2] += tb * w.z;
                ha[4 * jj + 3] += ta * w.w; hb[4 * jj + 3] += tb * w.w;
            }
        }
        #pragma unroll
        for (int j = 0; j < 32; j++) { ha[j] = fmaxf(ha[j], 0.f); hb[j] = fmaxf(hb[j], 0.f); }

        float dax = sm.prev[0] - pax, day = sm.prev[1] - pay, daz = sm.prev[2] - paz;
        float dbx = sm.prev[0] - pbx, dby = sm.prev[1] - pby, dbz = sm.prev[2] - pbz;
        float dba = (dax * dax + day * day + daz * daz) * sm.inv2s2;
        float dbb = (dbx * dbx + dby * dby + dbz * dbz) * sm.inv2s2;

        float sa[NRSS], sb[NRSS];
        #pragma unroll
        for (int q = 0; q < NRSS; q++) {
            float aa = sm.qc[q], ab = aa;
            const float4* wp = (const float4*)&sm.Qh[q * 32];
            #pragma unroll
            for (int jj = 0; jj < 8; jj++) {
                float4 w = wp[jj];
                aa += w.x * ha[4 * jj] + w.y * ha[4 * jj + 1] + w.z * ha[4 * jj + 2] + w.w * ha[4 * jj + 3];
                ab += w.x * hb[4 * jj] + w.y * hb[4 * jj + 1] + w.z * hb[4 * jj + 2] + w.w * hb[4 * jj + 3];
            }
            sa[q] = ((mba >> q) & 1) ? (aa - dba) : NEG_INF;
            sb[q] = ((mbb >> q) & 1) ? (ab - dbb) : NEG_INF;
        }

        // softmax over 256 LEDs: 2 barriers, local 4-partial reduce
        #pragma unroll
        for (int q = 0; q < NRSS; q++) {
            float m = wredmax(fmaxf(sa[q], sb[q]));
            if (lane == 0) sm.red[q * 4 + wid] = m;
        }
        __syncthreads();
        #pragma unroll
        for (int q = 0; q < NRSS; q++) {
            float m = fmaxf(fmaxf(sm.red[q * 4], sm.red[q * 4 + 1]),
                            fmaxf(sm.red[q * 4 + 2], sm.red[q * 4 + 3]));
            float ea = __expf(sa[q] - m), eb = __expf(sb[q] - m);
            sa[q] = ea; sb[q] = eb;
            float s = wredsum(ea + eb);
            if (lane == 0) sm.red[48 + q * 4 + wid] = s;
        }
        __syncthreads();
        #pragma unroll
        for (int q = 0; q < NRSS; q++) {
            float s = (sm.red[48 + q * 4] + sm.red[48 + q * 4 + 1]) +
                      (sm.red[48 + q * 4 + 2] + sm.red[48 + q * 4 + 3]);
            float inv = __frcp_rn(s);
            size_t base = ((size_t)b * NRSS + q) << 8;
            out[base + tid] = sa[q] * inv;
            out[base + tid + 128] = sb[q] * inv;
        }
        // next-iter load phase writes Ls/rss/prev, all last read before the two
        // softmax barriers above; red[48..] reads are separated from next-iter
        // red[48..] writes by the load barrier + max barrier. No trailing sync.
    }
}

extern "C" void kernel_launch(void* const* d_in, const int* in_sizes, int n_in,
                              void* d_out, int out_size) {
    (void)in_sizes; (void)n_in; (void)out_size;
    const float* rss_t  = (const float*)d_in[0];
    const float* led_f  = (const float*)d_in[1];
    const float* led_p  = (const float*)d_in[2];
    const float* prevp  = (const float*)d_in[3];
    const int*   fmask  = (const int*)  d_in[4];
    const float* lstm   = (const float*)d_in[5];
    const float* me_w1  = (const float*)d_in[6];
    const float* me_b1  = (const float*)d_in[7];
    const float* me_w2  = (const float*)d_in[8];
    const float* me_b2  = (const float*)d_in[9];
    const float* ci_w   = (const float*)d_in[10];
    const float* ci_b   = (const float*)d_in[11];
    const float* qf_w1  = (const float*)d_in[12];
    const float* qf_b1  = (const float*)d_in[13];
    const float* qf_w2  = (const float*)d_in[14];
    const float* qf_b2  = (const float*)d_in[15];
    const float* kp_w1  = (const float*)d_in[16];
    const float* kp_b1  = (const float*)d_in[17];
    const float* kp_w2  = (const float*)d_in[18];
    const float* kp_b2  = (const float*)d_in[19];
    const float* ss_w   = (const float*)d_in[20];
    const float* ss_b   = (const float*)d_in[21];
    float* out = (float*)d_out;

    static int smem_set = 0;
    if (!smem_set) {
        cudaFuncSetAttribute(cah_kernel, cudaFuncAttributeMaxDynamicSharedMemorySize,
                             (int)sizeof(SMem));
        smem_set = 1;
    }

    fold_kernel<<<8, 256>>>(qf_w2, qf_b2, kp_w2, kp_b2);
    cah_kernel<<<NBLK, NT, sizeof(SMem)>>>(rss_t, led_f, led_p, prevp, fmask, lstm,
                                           me_w1, me_b1, me_w2, me_b2, ci_w, ci_b,
                                           qf_w1, qf_b1, kp_w1, kp_b1, ss_w, ss_b, out);
}